// round 14
// baseline (speedup 1.0000x reference)
#include <cuda_runtime.h>
#include <cuda_bf16.h>
#include <mma.h>
#include <cstdint>

using namespace nvcuda;

// ---------------- problem constants ----------------
#define NROWS 65536        // 4 * 4096 * 4
#define NSAMP 2048
#define CC 64
#define C2 32
#define HW 4096
#define KB 102             // 6 blocks * 17
#define KP 112             // padded to 7 k-steps of 16
#define LOGVAR_MIN (-30.0f)
#define LOGVAR_MAX (20.0f)

// tiling: CTA = 128 rows x 2048 samples
#define CTA_M 128
#define TILE_N 128
#define NTILES 16          // 2048 / 128
#define RS_EL 136          // 272B row stride = 17 x 16B (odd) -> conflict-free ldmatrix
#define RS_B  272
#define SMEM_PROBE 0                        // 16x16 float = 1024 B
#define SMEM_MERGE 1024                     // 128 x ull = 1024 B
#define SMEM_A     2048                     // 128*272 = 34816 B
#define SMEM_Bo    (SMEM_A + CTA_M * RS_B)  // 36864
#define SMEM_BT    (128 * RS_B)             // 34816 B per buffer
#define SMEM_TOTAL (SMEM_Bo + 2 * SMEM_BT)  // 106496 B

// ---------------- device globals ----------------
__device__ __align__(16) unsigned short g_B[NSAMP * KP];  // bf16 bits, [n][112], 224B rows

// ---------------- helpers ----------------
__device__ __forceinline__ uint32_t smem_u32(const void* p) {
    uint32_t a;
    asm("{ .reg .u64 t; cvta.to.shared.u64 t, %1; cvt.u32.u64 %0, t; }" : "=r"(a) : "l"(p));
    return a;
}
__device__ __forceinline__ void cp16(uint32_t dst, const void* src) {
    asm volatile("cp.async.cg.shared.global [%0], [%1], 16;" :: "r"(dst), "l"(src));
}
#define CP_COMMIT() asm volatile("cp.async.commit_group;" ::: "memory")
#define CP_WAIT0()  asm volatile("cp.async.wait_group 0;" ::: "memory")

// bf16 triple split: x = h0 + h1 + h2 (residual subtractions exact in fp32)
__device__ __forceinline__ void split3(float x, unsigned short* h) {
    __nv_bfloat16 b1 = __float2bfloat16_rn(x);
    float r1 = x - __bfloat162float(b1);
    __nv_bfloat16 b2 = __float2bfloat16_rn(r1);
    float r2 = r1 - __bfloat162float(b2);
    __nv_bfloat16 b3 = __float2bfloat16_rn(r2);
    union { __nv_bfloat16 b; unsigned short u; } u1, u2, u3;
    u1.b = b1; u2.b = b2; u3.b = b3;
    h[0] = u1.u; h[1] = u2.u; h[2] = u3.u;
}

// monotonic ordering key: higher score wins; ties -> lower sample index wins
__device__ __forceinline__ unsigned long long make_key(float s, int idx) {
    uint32_t u = __float_as_uint(s);
    u = ((int)u < 0) ? ~u : (u | 0x80000000u);
    return ((unsigned long long)u << 32) | (unsigned long long)(NSAMP - 1 - idx);
}

// ---------------- Kernel A: build split B operand ----------------
// y[e] e=0..7: s2_g ; e=8..15: s_g ; e=16: 0.5*sum(s2)
// blocks j=0..5: A-level {0,0,1,0,1,2}, B-level {0,1,0,2,1,0}
__global__ void prep_B_kernel(const float* __restrict__ prior) {
    int n = blockIdx.x * blockDim.x + threadIdx.x;
    if (n >= NSAMP) return;
    const float4* pr = reinterpret_cast<const float4*>(prior + n * 8);
    float4 s0 = pr[0], s1 = pr[1];
    float s[8] = {s0.x, s0.y, s0.z, s0.w, s1.x, s1.y, s1.z, s1.w};
    float y[17];
    float sum2 = 0.f;
#pragma unroll
    for (int g = 0; g < 8; g++) { y[g] = s[g] * s[g]; y[8 + g] = s[g]; sum2 += y[g]; }
    y[16] = 0.5f * sum2;

    const int blev[6] = {0, 1, 0, 2, 1, 0};
    unsigned short row[KP];
#pragma unroll
    for (int k = 0; k < KP; k++) row[k] = 0;
#pragma unroll
    for (int e = 0; e < 17; e++) {
        unsigned short h[3];
        split3(y[e], h);
#pragma unroll
        for (int j = 0; j < 6; j++) row[j * 17 + e] = h[blev[j]];
    }
    uint4* dst = reinterpret_cast<uint4*>(g_B + (size_t)n * KP);
    const uint4* srcv = reinterpret_cast<const uint4*>(row);
#pragma unroll
    for (int i = 0; i < KP / 8; i++) dst[i] = srcv[i];
}

// ---------------- Kernel B: wmma GEMM (hoisted A frags) + probed argmax + scatter --
// grid = 512 CTAs: 128 rows x 2048 samples each. 256 threads = 8 warps (4 M x 2 N).
__global__ __launch_bounds__(256, 1)
void score_kernel(const float* __restrict__ z, const float* __restrict__ prior,
                  float* __restrict__ out) {
    extern __shared__ char smem[];
    const uint32_t smem_base = smem_u32(smem);
    float* probe = reinterpret_cast<float*>(smem + SMEM_PROBE);
    unsigned long long* merge = reinterpret_cast<unsigned long long*>(smem + SMEM_MERGE);
    __nv_bfloat16* sA = reinterpret_cast<__nv_bfloat16*>(smem + SMEM_A);
    __nv_bfloat16* sB = reinterpret_cast<__nv_bfloat16*>(smem + SMEM_Bo);

    const int tid = threadIdx.x;
    const int warp = tid >> 5;
    const int wm = warp >> 1;     // 0..3: M group of 32 rows
    const int wn = warp & 1;      // 0..1: N group of 64 cols
    const int rbase = blockIdx.x * CTA_M;

    probe[tid] = (float)tid;
    if (tid < 128) merge[tid] = 0ull;

    // ---- start async load of B tile 0 into buf0 ----
    {
        const char* src = reinterpret_cast<const char*>(g_B);
#pragma unroll
        for (int i = 0; i < 7; i++) {
            int idx = tid + i * 256;            // 1792 = 128 rows * 14 chunks
            int row = idx / 14, col = idx % 14;
            cp16(smem_base + SMEM_Bo + row * RS_B + col * 16, src + row * 224 + col * 16);
        }
        CP_COMMIT();
    }

    // ---- build A row (one row per thread, threads 0..127) ----
    if (tid < 128) {
        const int r = rbase + tid;
        const int b = r >> 14;
        const int rem = r & 16383;
        const int p = rem >> 2;
        const int ns = rem & 3;
        const float* zb = z + ((size_t)b * CC) * HW + p;
        float xv[17];
#pragma unroll
        for (int g = 0; g < 8; g++) {
            int ch = g * 4 + ns;
            float mu = __ldg(zb + (size_t)ch * HW);
            float lv = __ldg(zb + (size_t)(ch + C2) * HW);
            lv = fminf(fmaxf(lv, LOGVAR_MIN), LOGVAR_MAX);
            float iv = expf(-lv);
            xv[g] = -0.5f * iv;
            xv[8 + g] = mu * iv;
        }
        xv[16] = 1.0f;

        const int alev[6] = {0, 0, 1, 0, 1, 2};
        unsigned short* arow = reinterpret_cast<unsigned short*>(sA) + tid * RS_EL;
#pragma unroll
        for (int e = 0; e < 17; e++) {
            unsigned short h[3];
            split3(xv[e], h);
#pragma unroll
            for (int j = 0; j < 6; j++) arow[j * 17 + e] = h[alev[j]];
        }
#pragma unroll
        for (int k = KB; k < KP; k++) arow[k] = 0;
    }
    __syncthreads();

    // ---- probe accumulator layout ----
    uint32_t pcolPack = 0, rowBits = 0;
    int prow0, prow1, pcol0;
    {
        wmma::fragment<wmma::accumulator, 16, 16, 16, float> pf;
        wmma::load_matrix_sync(pf, probe, 16, wmma::mem_row_major);
        int r0 = ((int)pf.x[0]) >> 4;
        prow0 = r0; prow1 = r0;
        pcol0 = ((int)pf.x[0]) & 15;
#pragma unroll
        for (int k = 0; k < 8; k++) {
            int v = (int)pf.x[k];
            int pr = v >> 4, pc = v & 15;
            pcolPack |= (uint32_t)pc << (4 * k);
            if (pr != r0) { rowBits |= 1u << k; prow1 = pr; }
        }
    }
    // fast path check: rows {2,3,6,7}=+8, cols {c,c+1,c,c+1,c+8,c+9,c+8,c+9}
    bool ok = (rowBits == 0xCCu) && (prow1 == prow0 + 8);
    {
        int c1 = (int)((pcolPack >> 4) & 15u), c2 = (int)((pcolPack >> 8) & 15u);
        int c3 = (int)((pcolPack >> 12) & 15u), c4 = (int)((pcolPack >> 16) & 15u);
        int c5 = (int)((pcolPack >> 20) & 15u), c6 = (int)((pcolPack >> 24) & 15u);
        int c7 = (int)((pcolPack >> 28) & 15u);
        ok = ok && (c1 == pcol0 + 1) && (c2 == pcol0) && (c3 == pcol0 + 1)
                && (c4 == pcol0 + 8) && (c5 == pcol0 + 9) && (c6 == pcol0 + 8) && (c7 == pcol0 + 9);
    }
    const bool fast = __all_sync(0xFFFFFFFFu, ok ? 1 : 0);

    // ---- hoist A fragments into registers (invariant across n-tiles) ----
    wmma::fragment<wmma::matrix_a, 16, 16, 16, __nv_bfloat16, wmma::row_major> af[2][7];
    {
        const __nv_bfloat16* Aw = sA + (wm * 32) * RS_EL;
#pragma unroll
        for (int ks = 0; ks < 7; ks++) {
            wmma::load_matrix_sync(af[0][ks], Aw + ks * 16, RS_EL);
            wmma::load_matrix_sync(af[1][ks], Aw + 16 * RS_EL + ks * 16, RS_EL);
        }
    }

    const float NEG_INF = __int_as_float(0xff800000);
    float best[2][2];
    int bidx[2][2];
#pragma unroll
    for (int mi = 0; mi < 2; mi++)
#pragma unroll
        for (int t = 0; t < 2; t++) { best[mi][t] = NEG_INF; bidx[mi][t] = 0; }

    wmma::fragment<wmma::accumulator, 16, 16, 16, float> acc[2][4];

    for (int nt = 0; nt < NTILES; nt++) {
        const int buf = nt & 1;
        if (nt + 1 < NTILES) {
            const char* src = reinterpret_cast<const char*>(g_B) + (size_t)(nt + 1) * TILE_N * 224;
            uint32_t dstb = smem_base + SMEM_Bo + (buf ^ 1) * SMEM_BT;
#pragma unroll
            for (int i = 0; i < 7; i++) {
                int idx = tid + i * 256;
                int row = idx / 14, col = idx % 14;
                cp16(dstb + row * RS_B + col * 16, src + row * 224 + col * 16);
            }
            CP_COMMIT();
        }

#pragma unroll
        for (int mi = 0; mi < 2; mi++)
#pragma unroll
            for (int ni = 0; ni < 4; ni++)
                wmma::fill_fragment(acc[mi][ni], 0.0f);

        const __nv_bfloat16* Bw = sB + buf * (SMEM_BT / 2) + (wn * 64) * RS_EL;

#pragma unroll
        for (int ks = 0; ks < 7; ks++) {
#pragma unroll
            for (int ni = 0; ni < 4; ni++) {
                wmma::fragment<wmma::matrix_b, 16, 16, 16, __nv_bfloat16, wmma::col_major> bf;
                wmma::load_matrix_sync(bf, Bw + (ni * 16) * RS_EL + ks * 16, RS_EL);
                wmma::mma_sync(acc[0][ni], af[0][ks], bf, acc[0][ni]);
                wmma::mma_sync(acc[1][ni], af[1][ks], bf, acc[1][ni]);
            }
        }

        if (fast) {
            // per row-slot: depth-4 tree max, then in-tile first-occurrence column
            const int cb = nt * TILE_N + wn * 64 + pcol0;
#pragma unroll
            for (int mi = 0; mi < 2; mi++) {
                float m0 = NEG_INF, m1 = NEG_INF;
#pragma unroll
                for (int ni = 0; ni < 4; ni++) {
                    const float* x = acc[mi][ni].x;
                    m0 = fmaxf(m0, fmaxf(fmaxf(x[0], x[1]), fmaxf(x[4], x[5])));
                    m1 = fmaxf(m1, fmaxf(fmaxf(x[2], x[3]), fmaxf(x[6], x[7])));
                }
                if (m0 > best[mi][0]) {
                    best[mi][0] = m0;
                    int c = 0x7FFFFFFF;
#pragma unroll
                    for (int ni = 0; ni < 4; ni++) {
                        const float* x = acc[mi][ni].x;
                        const int c0 = cb + ni * 16;
                        if (x[0] == m0) c = min(c, c0);
                        if (x[1] == m0) c = min(c, c0 + 1);
                        if (x[4] == m0) c = min(c, c0 + 8);
                        if (x[5] == m0) c = min(c, c0 + 9);
                    }
                    bidx[mi][0] = c;
                }
                if (m1 > best[mi][1]) {
                    best[mi][1] = m1;
                    int c = 0x7FFFFFFF;
#pragma unroll
                    for (int ni = 0; ni < 4; ni++) {
                        const float* x = acc[mi][ni].x;
                        const int c0 = cb + ni * 16;
                        if (x[2] == m1) c = min(c, c0);
                        if (x[3] == m1) c = min(c, c0 + 1);
                        if (x[6] == m1) c = min(c, c0 + 8);
                        if (x[7] == m1) c = min(c, c0 + 9);
                    }
                    bidx[mi][1] = c;
                }
            }
        } else {
            // generic fallback: exact per-value tracker (round-8 proven)
#pragma unroll
            for (int mi = 0; mi < 2; mi++)
#pragma unroll
                for (int ni = 0; ni < 4; ni++) {
                    const int cbase = nt * TILE_N + wn * 64 + ni * 16;
#pragma unroll
                    for (int k = 0; k < 8; k++) {
                        float v = acc[mi][ni].x[k];
                        const int c = cbase + (int)((pcolPack >> (4 * k)) & 15u);
                        if (rowBits & (1u << k)) {
                            if (v > best[mi][1]) { best[mi][1] = v; bidx[mi][1] = c; }
                        } else {
                            if (v > best[mi][0]) { best[mi][0] = v; bidx[mi][0] = c; }
                        }
                    }
                }
        }

        CP_WAIT0();
        __syncthreads();
    }

    // ---- merge trackers into per-row keys (exact monotonic key) ----
#pragma unroll
    for (int mi = 0; mi < 2; mi++) {
        int r0 = wm * 32 + mi * 16 + prow0;
        int r1 = wm * 32 + mi * 16 + prow1;
        atomicMax(&merge[r0], make_key(best[mi][0], bidx[mi][0]));
        if (prow1 != prow0)
            atomicMax(&merge[r1], make_key(best[mi][1], bidx[mi][1]));
    }
    __syncthreads();

    // ---- scatter outputs (one row per thread, threads 0..127) ----
    if (tid < 128) {
        const int r = rbase + tid;
        unsigned long long key = merge[tid];
        const int id = NSAMP - 1 - (int)(key & 0xFFFFFFFFull);

        const int b = r >> 14;
        const int rem = r & 16383;
        const int p = rem >> 2;
        const int ns = rem & 3;
        const float* pr = prior + (size_t)id * 8;
        float* zo = out + ((size_t)b * C2) * HW + p;
#pragma unroll
        for (int g = 0; g < 8; g++)
            zo[(size_t)(g * 4 + ns) * HW] = __ldg(pr + g);
        out[(size_t)4 * C2 * HW + (((size_t)b * 4 + ns) * HW + p)] = (float)id;
    }
}

extern "C" void kernel_launch(void* const* d_in, const int* in_sizes, int n_in,
                              void* d_out, int out_size) {
    const float* z     = (const float*)d_in[0];
    const float* prior = (const float*)d_in[1];
    float* out = (float*)d_out;

    cudaFuncSetAttribute(score_kernel, cudaFuncAttributeMaxDynamicSharedMemorySize, SMEM_TOTAL);

    prep_B_kernel<<<(NSAMP + 255) / 256, 256>>>(prior);
    score_kernel<<<NROWS / CTA_M, 256, SMEM_TOTAL>>>(z, prior, out);
    (void)in_sizes; (void)n_in; (void)out_size;
}

// round 15
// speedup vs baseline: 1.0719x; 1.0719x over previous
#include <cuda_runtime.h>
#include <cuda_bf16.h>
#include <mma.h>
#include <cstdint>

using namespace nvcuda;

// ---------------- problem constants ----------------
#define NROWS 65536        // 4 * 4096 * 4
#define NSAMP 2048
#define CC 64
#define C2 32
#define HW 4096
#define KB 102             // 6 blocks * 17
#define KP 112             // padded to 7 k-steps of 16
#define LOGVAR_MIN (-30.0f)
#define LOGVAR_MAX (20.0f)

// tiling: CTA = 128 rows x 2048 samples, TILE_N=64 -> 3 CTAs/SM (24 warps)
#define CTA_M 128
#define TILE_N 64
#define NTILES 32          // 2048 / 64
#define RS_EL 136          // 272B row stride = 17 x 16B (odd) -> conflict-free ldmatrix
#define RS_B  272
#define SMEM_PROBE 0                        // 16x16 float = 1024 B
#define SMEM_MERGE 1024                     // 128 x ull = 1024 B
#define SMEM_A     2048                     // 128*272 = 34816 B
#define SMEM_Bo    (SMEM_A + CTA_M * RS_B)  // 36864
#define SMEM_BT    (TILE_N * RS_B)          // 17408 B per buffer
#define SMEM_TOTAL (SMEM_Bo + 2 * SMEM_BT)  // 71680 B -> 3 CTAs/SM

// ---------------- device globals ----------------
__device__ __align__(16) unsigned short g_B[NSAMP * KP];  // bf16 bits, [n][112], 224B rows

// ---------------- helpers ----------------
__device__ __forceinline__ uint32_t smem_u32(const void* p) {
    uint32_t a;
    asm("{ .reg .u64 t; cvta.to.shared.u64 t, %1; cvt.u32.u64 %0, t; }" : "=r"(a) : "l"(p));
    return a;
}
__device__ __forceinline__ void cp16(uint32_t dst, const void* src) {
    asm volatile("cp.async.cg.shared.global [%0], [%1], 16;" :: "r"(dst), "l"(src));
}
#define CP_COMMIT() asm volatile("cp.async.commit_group;" ::: "memory")
#define CP_WAIT0()  asm volatile("cp.async.wait_group 0;" ::: "memory")

// bf16 triple split: x = h0 + h1 + h2 (residual subtractions exact in fp32)
__device__ __forceinline__ void split3(float x, unsigned short* h) {
    __nv_bfloat16 b1 = __float2bfloat16_rn(x);
    float r1 = x - __bfloat162float(b1);
    __nv_bfloat16 b2 = __float2bfloat16_rn(r1);
    float r2 = r1 - __bfloat162float(b2);
    __nv_bfloat16 b3 = __float2bfloat16_rn(r2);
    union { __nv_bfloat16 b; unsigned short u; } u1, u2, u3;
    u1.b = b1; u2.b = b2; u3.b = b3;
    h[0] = u1.u; h[1] = u2.u; h[2] = u3.u;
}

// monotonic ordering key: higher score wins; ties -> lower sample index wins
__device__ __forceinline__ unsigned long long make_key(float s, int idx) {
    uint32_t u = __float_as_uint(s);
    u = ((int)u < 0) ? ~u : (u | 0x80000000u);
    return ((unsigned long long)u << 32) | (unsigned long long)(NSAMP - 1 - idx);
}

// ---------------- Kernel A: build split B operand ----------------
// y[e] e=0..7: s2_g ; e=8..15: s_g ; e=16: 0.5*sum(s2)
// blocks j=0..5: A-level {0,0,1,0,1,2}, B-level {0,1,0,2,1,0}
__global__ void prep_B_kernel(const float* __restrict__ prior) {
    int n = blockIdx.x * blockDim.x + threadIdx.x;
    if (n >= NSAMP) return;
    const float4* pr = reinterpret_cast<const float4*>(prior + n * 8);
    float4 s0 = pr[0], s1 = pr[1];
    float s[8] = {s0.x, s0.y, s0.z, s0.w, s1.x, s1.y, s1.z, s1.w};
    float y[17];
    float sum2 = 0.f;
#pragma unroll
    for (int g = 0; g < 8; g++) { y[g] = s[g] * s[g]; y[8 + g] = s[g]; sum2 += y[g]; }
    y[16] = 0.5f * sum2;

    const int blev[6] = {0, 1, 0, 2, 1, 0};
    unsigned short row[KP];
#pragma unroll
    for (int k = 0; k < KP; k++) row[k] = 0;
#pragma unroll
    for (int e = 0; e < 17; e++) {
        unsigned short h[3];
        split3(y[e], h);
#pragma unroll
        for (int j = 0; j < 6; j++) row[j * 17 + e] = h[blev[j]];
    }
    uint4* dst = reinterpret_cast<uint4*>(g_B + (size_t)n * KP);
    const uint4* srcv = reinterpret_cast<const uint4*>(row);
#pragma unroll
    for (int i = 0; i < KP / 8; i++) dst[i] = srcv[i];
}

// ---------------- Kernel B: wmma GEMM + probed argmax (tree epilogue) + scatter ----
// grid = 512 CTAs: 128 rows x 2048 samples. 256 threads = 8 warps (4 M x 2 N).
// Warp tile 32 rows x 32 cols -> acc[2][2]; 3 CTAs/SM = 24 warps for latency hiding.
__global__ __launch_bounds__(256, 3)
void score_kernel(const float* __restrict__ z, const float* __restrict__ prior,
                  float* __restrict__ out) {
    extern __shared__ char smem[];
    const uint32_t smem_base = smem_u32(smem);
    float* probe = reinterpret_cast<float*>(smem + SMEM_PROBE);
    unsigned long long* merge = reinterpret_cast<unsigned long long*>(smem + SMEM_MERGE);
    __nv_bfloat16* sA = reinterpret_cast<__nv_bfloat16*>(smem + SMEM_A);
    __nv_bfloat16* sB = reinterpret_cast<__nv_bfloat16*>(smem + SMEM_Bo);

    const int tid = threadIdx.x;
    const int warp = tid >> 5;
    const int wm = warp >> 1;     // 0..3: M group of 32 rows
    const int wn = warp & 1;      // 0..1: N group of 32 cols
    const int rbase = blockIdx.x * CTA_M;

    probe[tid] = (float)tid;
    if (tid < 128) merge[tid] = 0ull;

    // ---- start async load of B tile 0 into buf0 (64 rows x 14 chunks = 896) ----
    {
        const char* src = reinterpret_cast<const char*>(g_B);
#pragma unroll
        for (int i = 0; i < 4; i++) {
            int idx = tid + i * 256;
            if (idx < TILE_N * 14) {
                int row = idx / 14, col = idx % 14;
                cp16(smem_base + SMEM_Bo + row * RS_B + col * 16, src + row * 224 + col * 16);
            }
        }
        CP_COMMIT();
    }

    // ---- build A row (one row per thread, threads 0..127) ----
    if (tid < 128) {
        const int r = rbase + tid;
        const int b = r >> 14;
        const int rem = r & 16383;
        const int p = rem >> 2;
        const int ns = rem & 3;
        const float* zb = z + ((size_t)b * CC) * HW + p;
        float xv[17];
#pragma unroll
        for (int g = 0; g < 8; g++) {
            int ch = g * 4 + ns;
            float mu = __ldg(zb + (size_t)ch * HW);
            float lv = __ldg(zb + (size_t)(ch + C2) * HW);
            lv = fminf(fmaxf(lv, LOGVAR_MIN), LOGVAR_MAX);
            float iv = expf(-lv);
            xv[g] = -0.5f * iv;
            xv[8 + g] = mu * iv;
        }
        xv[16] = 1.0f;

        const int alev[6] = {0, 0, 1, 0, 1, 2};
        unsigned short* arow = reinterpret_cast<unsigned short*>(sA) + tid * RS_EL;
#pragma unroll
        for (int e = 0; e < 17; e++) {
            unsigned short h[3];
            split3(xv[e], h);
#pragma unroll
            for (int j = 0; j < 6; j++) arow[j * 17 + e] = h[alev[j]];
        }
#pragma unroll
        for (int k = KB; k < KP; k++) arow[k] = 0;
    }
    __syncthreads();

    // ---- probe accumulator layout ----
    uint32_t pcolPack = 0, rowBits = 0;
    int prow0, prow1, pcol0;
    {
        wmma::fragment<wmma::accumulator, 16, 16, 16, float> pf;
        wmma::load_matrix_sync(pf, probe, 16, wmma::mem_row_major);
        int r0 = ((int)pf.x[0]) >> 4;
        prow0 = r0; prow1 = r0;
        pcol0 = ((int)pf.x[0]) & 15;
#pragma unroll
        for (int k = 0; k < 8; k++) {
            int v = (int)pf.x[k];
            int pr = v >> 4, pc = v & 15;
            pcolPack |= (uint32_t)pc << (4 * k);
            if (pr != r0) { rowBits |= 1u << k; prow1 = pr; }
        }
    }
    // fast path check: rows {2,3,6,7}=+8, cols {c,c+1,c,c+1,c+8,c+9,c+8,c+9}
    bool ok = (rowBits == 0xCCu) && (prow1 == prow0 + 8);
    {
        int c1 = (int)((pcolPack >> 4) & 15u), c2 = (int)((pcolPack >> 8) & 15u);
        int c3 = (int)((pcolPack >> 12) & 15u), c4 = (int)((pcolPack >> 16) & 15u);
        int c5 = (int)((pcolPack >> 20) & 15u), c6 = (int)((pcolPack >> 24) & 15u);
        int c7 = (int)((pcolPack >> 28) & 15u);
        ok = ok && (c1 == pcol0 + 1) && (c2 == pcol0) && (c3 == pcol0 + 1)
                && (c4 == pcol0 + 8) && (c5 == pcol0 + 9) && (c6 == pcol0 + 8) && (c7 == pcol0 + 9);
    }
    const bool fast = __all_sync(0xFFFFFFFFu, ok ? 1 : 0);

    const float NEG_INF = __int_as_float(0xff800000);
    float best[2][2];
    int bidx[2][2];
#pragma unroll
    for (int mi = 0; mi < 2; mi++)
#pragma unroll
        for (int t = 0; t < 2; t++) { best[mi][t] = NEG_INF; bidx[mi][t] = 0; }

    wmma::fragment<wmma::accumulator, 16, 16, 16, float> acc[2][2];

    for (int nt = 0; nt < NTILES; nt++) {
        const int buf = nt & 1;
        if (nt + 1 < NTILES) {
            const char* src = reinterpret_cast<const char*>(g_B) + (size_t)(nt + 1) * TILE_N * 224;
            uint32_t dstb = smem_base + SMEM_Bo + (buf ^ 1) * SMEM_BT;
#pragma unroll
            for (int i = 0; i < 4; i++) {
                int idx = tid + i * 256;
                if (idx < TILE_N * 14) {
                    int row = idx / 14, col = idx % 14;
                    cp16(dstb + row * RS_B + col * 16, src + row * 224 + col * 16);
                }
            }
            CP_COMMIT();
        }

#pragma unroll
        for (int mi = 0; mi < 2; mi++)
#pragma unroll
            for (int ni = 0; ni < 2; ni++)
                wmma::fill_fragment(acc[mi][ni], 0.0f);

        const __nv_bfloat16* Bw = sB + buf * (SMEM_BT / 2) + (wn * 32) * RS_EL;
        const __nv_bfloat16* Aw = sA + (wm * 32) * RS_EL;

#pragma unroll
        for (int ks = 0; ks < 7; ks++) {
            wmma::fragment<wmma::matrix_a, 16, 16, 16, __nv_bfloat16, wmma::row_major> af[2];
            wmma::load_matrix_sync(af[0], Aw + ks * 16, RS_EL);
            wmma::load_matrix_sync(af[1], Aw + 16 * RS_EL + ks * 16, RS_EL);
#pragma unroll
            for (int ni = 0; ni < 2; ni++) {
                wmma::fragment<wmma::matrix_b, 16, 16, 16, __nv_bfloat16, wmma::col_major> bf;
                wmma::load_matrix_sync(bf, Bw + (ni * 16) * RS_EL + ks * 16, RS_EL);
                wmma::mma_sync(acc[0][ni], af[0], bf, acc[0][ni]);
                wmma::mma_sync(acc[1][ni], af[1], bf, acc[1][ni]);
            }
        }

        if (fast) {
            // per row-slot: tree max, then in-tile first-occurrence column
            const int cb = nt * TILE_N + wn * 32 + pcol0;
#pragma unroll
            for (int mi = 0; mi < 2; mi++) {
                float m0 = NEG_INF, m1 = NEG_INF;
#pragma unroll
                for (int ni = 0; ni < 2; ni++) {
                    const float* x = acc[mi][ni].x;
                    m0 = fmaxf(m0, fmaxf(fmaxf(x[0], x[1]), fmaxf(x[4], x[5])));
                    m1 = fmaxf(m1, fmaxf(fmaxf(x[2], x[3]), fmaxf(x[6], x[7])));
                }
                if (m0 > best[mi][0]) {
                    best[mi][0] = m0;
                    int c = 0x7FFFFFFF;
#pragma unroll
                    for (int ni = 0; ni < 2; ni++) {
                        const float* x = acc[mi][ni].x;
                        const int c0 = cb + ni * 16;
                        if (x[0] == m0) c = min(c, c0);
                        if (x[1] == m0) c = min(c, c0 + 1);
                        if (x[4] == m0) c = min(c, c0 + 8);
                        if (x[5] == m0) c = min(c, c0 + 9);
                    }
                    bidx[mi][0] = c;
                }
                if (m1 > best[mi][1]) {
                    best[mi][1] = m1;
                    int c = 0x7FFFFFFF;
#pragma unroll
                    for (int ni = 0; ni < 2; ni++) {
                        const float* x = acc[mi][ni].x;
                        const int c0 = cb + ni * 16;
                        if (x[2] == m1) c = min(c, c0);
                        if (x[3] == m1) c = min(c, c0 + 1);
                        if (x[6] == m1) c = min(c, c0 + 8);
                        if (x[7] == m1) c = min(c, c0 + 9);
                    }
                    bidx[mi][1] = c;
                }
            }
        } else {
            // generic fallback: exact per-value tracker (round-8 proven)
#pragma unroll
            for (int mi = 0; mi < 2; mi++)
#pragma unroll
                for (int ni = 0; ni < 2; ni++) {
                    const int cbase = nt * TILE_N + wn * 32 + ni * 16;
#pragma unroll
                    for (int k = 0; k < 8; k++) {
                        float v = acc[mi][ni].x[k];
                        const int c = cbase + (int)((pcolPack >> (4 * k)) & 15u);
                        if (rowBits & (1u << k)) {
                            if (v > best[mi][1]) { best[mi][1] = v; bidx[mi][1] = c; }
                        } else {
                            if (v > best[mi][0]) { best[mi][0] = v; bidx[mi][0] = c; }
                        }
                    }
                }
        }

        CP_WAIT0();
        __syncthreads();
    }

    // ---- merge trackers into per-row keys (exact monotonic key) ----
#pragma unroll
    for (int mi = 0; mi < 2; mi++) {
        int r0 = wm * 32 + mi * 16 + prow0;
        int r1 = wm * 32 + mi * 16 + prow1;
        atomicMax(&merge[r0], make_key(best[mi][0], bidx[mi][0]));
        if (prow1 != prow0)
            atomicMax(&merge[r1], make_key(best[mi][1], bidx[mi][1]));
    }
    __syncthreads();

    // ---- scatter outputs (one row per thread, threads 0..127) ----
    if (tid < 128) {
        const int r = rbase + tid;
        unsigned long long key = merge[tid];
        const int id = NSAMP - 1 - (int)(key & 0xFFFFFFFFull);

        const int b = r >> 14;
        const int rem = r & 16383;
        const int p = rem >> 2;
        const int ns = rem & 3;
        const float* pr = prior + (size_t)id * 8;
        float* zo = out + ((size_t)b * C2) * HW + p;
#pragma unroll
        for (int g = 0; g < 8; g++)
            zo[(size_t)(g * 4 + ns) * HW] = __ldg(pr + g);
        out[(size_t)4 * C2 * HW + (((size_t)b * 4 + ns) * HW + p)] = (float)id;
    }
}

extern "C" void kernel_launch(void* const* d_in, const int* in_sizes, int n_in,
                              void* d_out, int out_size) {
    const float* z     = (const float*)d_in[0];
    const float* prior = (const float*)d_in[1];
    float* out = (float*)d_out;

    cudaFuncSetAttribute(score_kernel, cudaFuncAttributeMaxDynamicSharedMemorySize, SMEM_TOTAL);

    prep_B_kernel<<<(NSAMP + 255) / 256, 256>>>(prior);
    score_kernel<<<NROWS / CTA_M, 256, SMEM_TOTAL>>>(z, prior, out);
    (void)in_sizes; (void)n_in; (void)out_size;
}

// round 16
// speedup vs baseline: 1.1596x; 1.0818x over previous
#include <cuda_runtime.h>
#include <cuda_bf16.h>
#include <mma.h>
#include <cstdint>

using namespace nvcuda;

// ---------------- problem constants ----------------
#define NROWS 65536        // 4 * 4096 * 4
#define NSAMP 2048
#define CC 64
#define C2 32
#define HW 4096
#define KB 102             // 6 blocks * 17
#define KP 112             // padded to 7 k-steps of 16
#define LOGVAR_MIN (-30.0f)
#define LOGVAR_MAX (20.0f)

// tiling: CTA = 128 rows x 2048 samples, 2 CTAs/SM (the R11 optimum)
#define CTA_M 128
#define TILE_N 128
#define NTILES 16          // 2048 / 128
#define RS_EL 136          // 272B row stride = 17 x 16B (odd) -> conflict-free ldmatrix
#define RS_B  272
#define SMEM_PROBE 0                        // 16x16 float = 1024 B
#define SMEM_MERGE 1024                     // 128 x ull = 1024 B
#define SMEM_A     2048                     // 128*272 = 34816 B
#define SMEM_Bo    (SMEM_A + CTA_M * RS_B)  // 36864
#define SMEM_BT    (128 * RS_B)             // 34816 B per buffer
#define SMEM_TOTAL (SMEM_Bo + 2 * SMEM_BT)  // 106496 B -> 2 CTAs/SM

// ---------------- device globals ----------------
__device__ __align__(16) unsigned short g_B[NSAMP * KP];  // bf16 bits, [n][112], 224B rows

// ---------------- helpers ----------------
__device__ __forceinline__ uint32_t smem_u32(const void* p) {
    uint32_t a;
    asm("{ .reg .u64 t; cvta.to.shared.u64 t, %1; cvt.u32.u64 %0, t; }" : "=r"(a) : "l"(p));
    return a;
}
__device__ __forceinline__ void cp16(uint32_t dst, const void* src) {
    asm volatile("cp.async.cg.shared.global [%0], [%1], 16;" :: "r"(dst), "l"(src));
}
#define CP_COMMIT() asm volatile("cp.async.commit_group;" ::: "memory")
#define CP_WAIT0()  asm volatile("cp.async.wait_group 0;" ::: "memory")

// bf16 triple split: x = h0 + h1 + h2 (residual subtractions exact in fp32)
__device__ __forceinline__ void split3(float x, unsigned short* h) {
    __nv_bfloat16 b1 = __float2bfloat16_rn(x);
    float r1 = x - __bfloat162float(b1);
    __nv_bfloat16 b2 = __float2bfloat16_rn(r1);
    float r2 = r1 - __bfloat162float(b2);
    __nv_bfloat16 b3 = __float2bfloat16_rn(r2);
    union { __nv_bfloat16 b; unsigned short u; } u1, u2, u3;
    u1.b = b1; u2.b = b2; u3.b = b3;
    h[0] = u1.u; h[1] = u2.u; h[2] = u3.u;
}

// monotonic ordering key: higher score wins; ties -> lower sample index wins
__device__ __forceinline__ unsigned long long make_key(float s, int idx) {
    uint32_t u = __float_as_uint(s);
    u = ((int)u < 0) ? ~u : (u | 0x80000000u);
    return ((unsigned long long)u << 32) | (unsigned long long)(NSAMP - 1 - idx);
}

// ---------------- Kernel A: build split B operand ----------------
// y[e] e=0..7: s2_g ; e=8..15: s_g ; e=16: 0.5*sum(s2)
// blocks j=0..5: A-level {0,0,1,0,1,2}, B-level {0,1,0,2,1,0}
__global__ void prep_B_kernel(const float* __restrict__ prior) {
    int n = blockIdx.x * blockDim.x + threadIdx.x;
    if (n >= NSAMP) return;
    const float4* pr = reinterpret_cast<const float4*>(prior + n * 8);
    float4 s0 = pr[0], s1 = pr[1];
    float s[8] = {s0.x, s0.y, s0.z, s0.w, s1.x, s1.y, s1.z, s1.w};
    float y[17];
    float sum2 = 0.f;
#pragma unroll
    for (int g = 0; g < 8; g++) { y[g] = s[g] * s[g]; y[8 + g] = s[g]; sum2 += y[g]; }
    y[16] = 0.5f * sum2;

    const int blev[6] = {0, 1, 0, 2, 1, 0};
    unsigned short row[KP];
#pragma unroll
    for (int k = 0; k < KP; k++) row[k] = 0;
#pragma unroll
    for (int e = 0; e < 17; e++) {
        unsigned short h[3];
        split3(y[e], h);
#pragma unroll
        for (int j = 0; j < 6; j++) row[j * 17 + e] = h[blev[j]];
    }
    uint4* dst = reinterpret_cast<uint4*>(g_B + (size_t)n * KP);
    const uint4* srcv = reinterpret_cast<const uint4*>(row);
#pragma unroll
    for (int i = 0; i < KP / 8; i++) dst[i] = srcv[i];
}

// ---------------- Kernel B: wmma GEMM (batched fragment loads) + probed argmax ----
// grid = 512 CTAs: 128 rows x 2048 samples. 256 threads = 8 warps (4 M x 2 N).
__global__ __launch_bounds__(256, 2)
void score_kernel(const float* __restrict__ z, const float* __restrict__ prior,
                  float* __restrict__ out) {
    extern __shared__ char smem[];
    const uint32_t smem_base = smem_u32(smem);
    float* probe = reinterpret_cast<float*>(smem + SMEM_PROBE);
    unsigned long long* merge = reinterpret_cast<unsigned long long*>(smem + SMEM_MERGE);
    __nv_bfloat16* sA = reinterpret_cast<__nv_bfloat16*>(smem + SMEM_A);
    __nv_bfloat16* sB = reinterpret_cast<__nv_bfloat16*>(smem + SMEM_Bo);

    const int tid = threadIdx.x;
    const int warp = tid >> 5;
    const int wm = warp >> 1;     // 0..3: M group of 32 rows
    const int wn = warp & 1;      // 0..1: N group of 64 cols
    const int rbase = blockIdx.x * CTA_M;

    probe[tid] = (float)tid;
    if (tid < 128) merge[tid] = 0ull;

    // ---- start async load of B tile 0 into buf0 ----
    {
        const char* src = reinterpret_cast<const char*>(g_B);
#pragma unroll
        for (int i = 0; i < 7; i++) {
            int idx = tid + i * 256;            // 1792 = 128 rows * 14 chunks
            int row = idx / 14, col = idx % 14;
            cp16(smem_base + SMEM_Bo + row * RS_B + col * 16, src + row * 224 + col * 16);
        }
        CP_COMMIT();
    }

    // ---- build A row (one row per thread, threads 0..127) ----
    if (tid < 128) {
        const int r = rbase + tid;
        const int b = r >> 14;
        const int rem = r & 16383;
        const int p = rem >> 2;
        const int ns = rem & 3;
        const float* zb = z + ((size_t)b * CC) * HW + p;
        float xv[17];
#pragma unroll
        for (int g = 0; g < 8; g++) {
            int ch = g * 4 + ns;
            float mu = __ldg(zb + (size_t)ch * HW);
            float lv = __ldg(zb + (size_t)(ch + C2) * HW);
            lv = fminf(fmaxf(lv, LOGVAR_MIN), LOGVAR_MAX);
            float iv = expf(-lv);
            xv[g] = -0.5f * iv;
            xv[8 + g] = mu * iv;
        }
        xv[16] = 1.0f;

        const int alev[6] = {0, 0, 1, 0, 1, 2};
        unsigned short* arow = reinterpret_cast<unsigned short*>(sA) + tid * RS_EL;
#pragma unroll
        for (int e = 0; e < 17; e++) {
            unsigned short h[3];
            split3(xv[e], h);
#pragma unroll
            for (int j = 0; j < 6; j++) arow[j * 17 + e] = h[alev[j]];
        }
#pragma unroll
        for (int k = KB; k < KP; k++) arow[k] = 0;
    }
    __syncthreads();

    // ---- probe accumulator layout ----
    uint32_t pcolPack = 0, rowBits = 0;
    int prow0, prow1, pcol0;
    {
        wmma::fragment<wmma::accumulator, 16, 16, 16, float> pf;
        wmma::load_matrix_sync(pf, probe, 16, wmma::mem_row_major);
        int r0 = ((int)pf.x[0]) >> 4;
        prow0 = r0; prow1 = r0;
        pcol0 = ((int)pf.x[0]) & 15;
#pragma unroll
        for (int k = 0; k < 8; k++) {
            int v = (int)pf.x[k];
            int pr = v >> 4, pc = v & 15;
            pcolPack |= (uint32_t)pc << (4 * k);
            if (pr != r0) { rowBits |= 1u << k; prow1 = pr; }
        }
    }
    // fast path check: rows {2,3,6,7}=+8, cols {c,c+1,c,c+1,c+8,c+9,c+8,c+9}
    bool ok = (rowBits == 0xCCu) && (prow1 == prow0 + 8);
    {
        int c1 = (int)((pcolPack >> 4) & 15u), c2 = (int)((pcolPack >> 8) & 15u);
        int c3 = (int)((pcolPack >> 12) & 15u), c4 = (int)((pcolPack >> 16) & 15u);
        int c5 = (int)((pcolPack >> 20) & 15u), c6 = (int)((pcolPack >> 24) & 15u);
        int c7 = (int)((pcolPack >> 28) & 15u);
        ok = ok && (c1 == pcol0 + 1) && (c2 == pcol0) && (c3 == pcol0 + 1)
                && (c4 == pcol0 + 8) && (c5 == pcol0 + 9) && (c6 == pcol0 + 8) && (c7 == pcol0 + 9);
    }
    const bool fast = __all_sync(0xFFFFFFFFu, ok ? 1 : 0);

    const float NEG_INF = __int_as_float(0xff800000);
    float best[2][2];
    int bidx[2][2];
#pragma unroll
    for (int mi = 0; mi < 2; mi++)
#pragma unroll
        for (int t = 0; t < 2; t++) { best[mi][t] = NEG_INF; bidx[mi][t] = 0; }

    wmma::fragment<wmma::accumulator, 16, 16, 16, float> acc[2][4];

    for (int nt = 0; nt < NTILES; nt++) {
        const int buf = nt & 1;
        if (nt + 1 < NTILES) {
            const char* src = reinterpret_cast<const char*>(g_B) + (size_t)(nt + 1) * TILE_N * 224;
            uint32_t dstb = smem_base + SMEM_Bo + (buf ^ 1) * SMEM_BT;
#pragma unroll
            for (int i = 0; i < 7; i++) {
                int idx = tid + i * 256;
                int row = idx / 14, col = idx % 14;
                cp16(dstb + row * RS_B + col * 16, src + row * 224 + col * 16);
            }
            CP_COMMIT();
        }

#pragma unroll
        for (int mi = 0; mi < 2; mi++)
#pragma unroll
            for (int ni = 0; ni < 4; ni++)
                wmma::fill_fragment(acc[mi][ni], 0.0f);

        const __nv_bfloat16* Bw = sB + buf * (SMEM_BT / 2) + (wn * 64) * RS_EL;
        const __nv_bfloat16* Aw = sA + (wm * 32) * RS_EL;

#pragma unroll
        for (int ks = 0; ks < 7; ks++) {
            // batch ALL fragment loads for this ks before any mma:
            // while mma on bf[0] waits, bf[1..3] are already loaded -> the
            // remaining 6 HMMA pairs issue back-to-back (one LDS latency per ks)
            wmma::fragment<wmma::matrix_a, 16, 16, 16, __nv_bfloat16, wmma::row_major> af[2];
            wmma::fragment<wmma::matrix_b, 16, 16, 16, __nv_bfloat16, wmma::col_major> bf[4];
            wmma::load_matrix_sync(af[0], Aw + ks * 16, RS_EL);
            wmma::load_matrix_sync(af[1], Aw + 16 * RS_EL + ks * 16, RS_EL);
#pragma unroll
            for (int ni = 0; ni < 4; ni++)
                wmma::load_matrix_sync(bf[ni], Bw + (ni * 16) * RS_EL + ks * 16, RS_EL);
#pragma unroll
            for (int ni = 0; ni < 4; ni++) {
                wmma::mma_sync(acc[0][ni], af[0], bf[ni], acc[0][ni]);
                wmma::mma_sync(acc[1][ni], af[1], bf[ni], acc[1][ni]);
            }
        }

        if (fast) {
            // per row-slot: depth-4 tree max, then in-tile first-occurrence column
            const int cb = nt * TILE_N + wn * 64 + pcol0;
#pragma unroll
            for (int mi = 0; mi < 2; mi++) {
                float m0 = NEG_INF, m1 = NEG_INF;
#pragma unroll
                for (int ni = 0; ni < 4; ni++) {
                    const float* x = acc[mi][ni].x;
                    m0 = fmaxf(m0, fmaxf(fmaxf(x[0], x[1]), fmaxf(x[4], x[5])));
                    m1 = fmaxf(m1, fmaxf(fmaxf(x[2], x[3]), fmaxf(x[6], x[7])));
                }
                if (m0 > best[mi][0]) {
                    best[mi][0] = m0;
                    int c = 0x7FFFFFFF;
#pragma unroll
                    for (int ni = 0; ni < 4; ni++) {
                        const float* x = acc[mi][ni].x;
                        const int c0 = cb + ni * 16;
                        if (x[0] == m0) c = min(c, c0);
                        if (x[1] == m0) c = min(c, c0 + 1);
                        if (x[4] == m0) c = min(c, c0 + 8);
                        if (x[5] == m0) c = min(c, c0 + 9);
                    }
                    bidx[mi][0] = c;
                }
                if (m1 > best[mi][1]) {
                    best[mi][1] = m1;
                    int c = 0x7FFFFFFF;
#pragma unroll
                    for (int ni = 0; ni < 4; ni++) {
                        const float* x = acc[mi][ni].x;
                        const int c0 = cb + ni * 16;
                        if (x[2] == m1) c = min(c, c0);
                        if (x[3] == m1) c = min(c, c0 + 1);
                        if (x[6] == m1) c = min(c, c0 + 8);
                        if (x[7] == m1) c = min(c, c0 + 9);
                    }
                    bidx[mi][1] = c;
                }
            }
        } else {
            // generic fallback: exact per-value tracker (round-8 proven)
#pragma unroll
            for (int mi = 0; mi < 2; mi++)
#pragma unroll
                for (int ni = 0; ni < 4; ni++) {
                    const int cbase = nt * TILE_N + wn * 64 + ni * 16;
#pragma unroll
                    for (int k = 0; k < 8; k++) {
                        float v = acc[mi][ni].x[k];
                        const int c = cbase + (int)((pcolPack >> (4 * k)) & 15u);
                        if (rowBits & (1u << k)) {
                            if (v > best[mi][1]) { best[mi][1] = v; bidx[mi][1] = c; }
                        } else {
                            if (v > best[mi][0]) { best[mi][0] = v; bidx[mi][0] = c; }
                        }
                    }
                }
        }

        CP_WAIT0();
        __syncthreads();
    }

    // ---- merge trackers into per-row keys (exact monotonic key) ----
#pragma unroll
    for (int mi = 0; mi < 2; mi++) {
        int r0 = wm * 32 + mi * 16 + prow0;
        int r1 = wm * 32 + mi * 16 + prow1;
        atomicMax(&merge[r0], make_key(best[mi][0], bidx[mi][0]));
        if (prow1 != prow0)
            atomicMax(&merge[r1], make_key(best[mi][1], bidx[mi][1]));
    }
    __syncthreads();

    // ---- scatter outputs (one row per thread, threads 0..127) ----
    if (tid < 128) {
        const int r = rbase + tid;
        unsigned long long key = merge[tid];
        const int id = NSAMP - 1 - (int)(key & 0xFFFFFFFFull);

        const int b = r >> 14;
        const int rem = r & 16383;
        const int p = rem >> 2;
        const int ns = rem & 3;
        const float* pr = prior + (size_t)id * 8;
        float* zo = out + ((size_t)b * C2) * HW + p;
#pragma unroll
        for (int g = 0; g < 8; g++)
            zo[(size_t)(g * 4 + ns) * HW] = __ldg(pr + g);
        out[(size_t)4 * C2 * HW + (((size_t)b * 4 + ns) * HW + p)] = (float)id;
    }
}

extern "C" void kernel_launch(void* const* d_in, const int* in_sizes, int n_in,
                              void* d_out, int out_size) {
    const float* z     = (const float*)d_in[0];
    const float* prior = (const float*)d_in[1];
    float* out = (float*)d_out;

    cudaFuncSetAttribute(score_kernel, cudaFuncAttributeMaxDynamicSharedMemorySize, SMEM_TOTAL);

    prep_B_kernel<<<(NSAMP + 255) / 256, 256>>>(prior);
    score_kernel<<<NROWS / CTA_M, 256, SMEM_TOTAL>>>(z, prior, out);
    (void)in_sizes; (void)n_in; (void)out_size;
}

// round 17
// speedup vs baseline: 2.1480x; 1.8524x over previous
#include <cuda_runtime.h>
#include <cuda_fp16.h>
#include <mma.h>
#include <cstdint>

using namespace nvcuda;

// ---------------- problem constants ----------------
#define NROWS 65536        // 4 * 4096 * 4
#define NSAMP 2048
#define CC 64
#define C2 32
#define HW 4096
#define KB 51              // 3 blocks * 17 (fp16 2-level split)
#define KP 64              // padded to 4 k-steps of 16
#define LOGVAR_MIN (-30.0f)
#define LOGVAR_MAX (20.0f)

// tiling: CTA = 128 rows x 2048 samples, 2 CTAs/SM (R11 structure)
#define CTA_M 128
#define TILE_N 128
#define NTILES 16          // 2048 / 128
#define RS_EL 72           // 144B row stride = 9 x 16B (odd) -> conflict-free ldmatrix
#define RS_B  144
#define GROW_B 128         // g_B row bytes (64 fp16)
#define SMEM_PROBE 0                        // 16x16 float = 1024 B
#define SMEM_MERGE 1024                     // 128 x ull = 1024 B
#define SMEM_A     2048                     // 128*144 = 18432 B
#define SMEM_Bo    (SMEM_A + CTA_M * RS_B)  // 20480
#define SMEM_BT    (128 * RS_B)             // 18432 B per buffer
#define SMEM_TOTAL (SMEM_Bo + 2 * SMEM_BT)  // 57344 B -> 2 CTAs/SM

// ---------------- device globals ----------------
__device__ __align__(16) unsigned short g_B[NSAMP * KP];  // fp16 bits, [n][64], 128B rows

// ---------------- helpers ----------------
__device__ __forceinline__ uint32_t smem_u32(const void* p) {
    uint32_t a;
    asm("{ .reg .u64 t; cvta.to.shared.u64 t, %1; cvt.u32.u64 %0, t; }" : "=r"(a) : "l"(p));
    return a;
}
__device__ __forceinline__ void cp16(uint32_t dst, const void* src) {
    asm volatile("cp.async.cg.shared.global [%0], [%1], 16;" :: "r"(dst), "l"(src));
}
#define CP_COMMIT() asm volatile("cp.async.commit_group;" ::: "memory")
#define CP_WAIT0()  asm volatile("cp.async.wait_group 0;" ::: "memory")

// fp16 2-level split: x = h0 + h1 + O(2^-24 x); residual subtraction exact in fp32
__device__ __forceinline__ void split2(float x, unsigned short* h) {
    __half a = __float2half_rn(x);
    float r = x - __half2float(a);
    __half b = __float2half_rn(r);
    union { __half v; unsigned short u; } u1, u2;
    u1.v = a; u2.v = b;
    h[0] = u1.u; h[1] = u2.u;
}

// monotonic ordering key: higher score wins; ties -> lower sample index wins
__device__ __forceinline__ unsigned long long make_key(float s, int idx) {
    uint32_t u = __float_as_uint(s);
    u = ((int)u < 0) ? ~u : (u | 0x80000000u);
    return ((unsigned long long)u << 32) | (unsigned long long)(NSAMP - 1 - idx);
}

// ---------------- Kernel A: build split B operand ----------------
// y[e] e=0..7: s2_g ; e=8..15: s_g ; e=16: 0.5*sum(s2)
// blocks j=0..2: A-level {x1, x1, x2}, B-level {y1, y2, y1}
__global__ void prep_B_kernel(const float* __restrict__ prior) {
    int n = blockIdx.x * blockDim.x + threadIdx.x;
    if (n >= NSAMP) return;
    const float4* pr = reinterpret_cast<const float4*>(prior + n * 8);
    float4 s0 = pr[0], s1 = pr[1];
    float s[8] = {s0.x, s0.y, s0.z, s0.w, s1.x, s1.y, s1.z, s1.w};
    float y[17];
    float sum2 = 0.f;
#pragma unroll
    for (int g = 0; g < 8; g++) { y[g] = s[g] * s[g]; y[8 + g] = s[g]; sum2 += y[g]; }
    y[16] = 0.5f * sum2;

    const int blev[3] = {0, 1, 0};
    unsigned short row[KP];
#pragma unroll
    for (int k = 0; k < KP; k++) row[k] = 0;
#pragma unroll
    for (int e = 0; e < 17; e++) {
        unsigned short h[2];
        split2(y[e], h);
#pragma unroll
        for (int j = 0; j < 3; j++) row[j * 17 + e] = h[blev[j]];
    }
    uint4* dst = reinterpret_cast<uint4*>(g_B + (size_t)n * KP);
    const uint4* srcv = reinterpret_cast<const uint4*>(row);
#pragma unroll
    for (int i = 0; i < KP / 8; i++) dst[i] = srcv[i];
}

// ---------------- Kernel B: fp16 wmma GEMM + probed argmax (tree epilogue) --------
// grid = 512 CTAs: 128 rows x 2048 samples. 256 threads = 8 warps (4 M x 2 N).
__global__ __launch_bounds__(256, 2)
void score_kernel(const float* __restrict__ z, const float* __restrict__ prior,
                  float* __restrict__ out) {
    extern __shared__ char smem[];
    const uint32_t smem_base = smem_u32(smem);
    float* probe = reinterpret_cast<float*>(smem + SMEM_PROBE);
    unsigned long long* merge = reinterpret_cast<unsigned long long*>(smem + SMEM_MERGE);
    __half* sA = reinterpret_cast<__half*>(smem + SMEM_A);
    __half* sB = reinterpret_cast<__half*>(smem + SMEM_Bo);

    const int tid = threadIdx.x;
    const int warp = tid >> 5;
    const int wm = warp >> 1;     // 0..3: M group of 32 rows
    const int wn = warp & 1;      // 0..1: N group of 64 cols
    const int rbase = blockIdx.x * CTA_M;

    probe[tid] = (float)tid;
    if (tid < 128) merge[tid] = 0ull;

    // ---- start async load of B tile 0 into buf0 (128 rows x 8 chunks = 1024) ----
    {
        const char* src = reinterpret_cast<const char*>(g_B);
#pragma unroll
        for (int i = 0; i < 4; i++) {
            int idx = tid + i * 256;
            int row = idx >> 3, col = idx & 7;
            cp16(smem_base + SMEM_Bo + row * RS_B + col * 16, src + row * GROW_B + col * 16);
        }
        CP_COMMIT();
    }

    // ---- build A row (one row per thread, threads 0..127) ----
    if (tid < 128) {
        const int r = rbase + tid;
        const int b = r >> 14;
        const int rem = r & 16383;
        const int p = rem >> 2;
        const int ns = rem & 3;
        const float* zb = z + ((size_t)b * CC) * HW + p;
        float xv[17];
#pragma unroll
        for (int g = 0; g < 8; g++) {
            int ch = g * 4 + ns;
            float mu = __ldg(zb + (size_t)ch * HW);
            float lv = __ldg(zb + (size_t)(ch + C2) * HW);
            lv = fminf(fmaxf(lv, LOGVAR_MIN), LOGVAR_MAX);
            float iv = expf(-lv);
            xv[g] = -0.5f * iv;
            xv[8 + g] = mu * iv;
        }
        xv[16] = 1.0f;

        const int alev[3] = {0, 0, 1};
        unsigned short* arow = reinterpret_cast<unsigned short*>(sA) + tid * RS_EL;
#pragma unroll
        for (int e = 0; e < 17; e++) {
            unsigned short h[2];
            split2(xv[e], h);
#pragma unroll
            for (int j = 0; j < 3; j++) arow[j * 17 + e] = h[alev[j]];
        }
#pragma unroll
        for (int k = KB; k < KP; k++) arow[k] = 0;   // zero pad k=51..63
    }
    __syncthreads();

    // ---- probe accumulator layout ----
    uint32_t pcolPack = 0, rowBits = 0;
    int prow0, prow1, pcol0;
    {
        wmma::fragment<wmma::accumulator, 16, 16, 16, float> pf;
        wmma::load_matrix_sync(pf, probe, 16, wmma::mem_row_major);
        int r0 = ((int)pf.x[0]) >> 4;
        prow0 = r0; prow1 = r0;
        pcol0 = ((int)pf.x[0]) & 15;
#pragma unroll
        for (int k = 0; k < 8; k++) {
            int v = (int)pf.x[k];
            int pr = v >> 4, pc = v & 15;
            pcolPack |= (uint32_t)pc << (4 * k);
            if (pr != r0) { rowBits |= 1u << k; prow1 = pr; }
        }
    }
    // fast path check: rows {2,3,6,7}=+8, cols {c,c+1,c,c+1,c+8,c+9,c+8,c+9}
    bool ok = (rowBits == 0xCCu) && (prow1 == prow0 + 8);
    {
        int c1 = (int)((pcolPack >> 4) & 15u), c2 = (int)((pcolPack >> 8) & 15u);
        int c3 = (int)((pcolPack >> 12) & 15u), c4 = (int)((pcolPack >> 16) & 15u);
        int c5 = (int)((pcolPack >> 20) & 15u), c6 = (int)((pcolPack >> 24) & 15u);
        int c7 = (int)((pcolPack >> 28) & 15u);
        ok = ok && (c1 == pcol0 + 1) && (c2 == pcol0) && (c3 == pcol0 + 1)
                && (c4 == pcol0 + 8) && (c5 == pcol0 + 9) && (c6 == pcol0 + 8) && (c7 == pcol0 + 9);
    }
    const bool fast = __all_sync(0xFFFFFFFFu, ok ? 1 : 0);

    const float NEG_INF = __int_as_float(0xff800000);
    float best[2][2];
    int bidx[2][2];
#pragma unroll
    for (int mi = 0; mi < 2; mi++)
#pragma unroll
        for (int t = 0; t < 2; t++) { best[mi][t] = NEG_INF; bidx[mi][t] = 0; }

    wmma::fragment<wmma::accumulator, 16, 16, 16, float> acc[2][4];

    for (int nt = 0; nt < NTILES; nt++) {
        const int buf = nt & 1;
        if (nt + 1 < NTILES) {
            const char* src = reinterpret_cast<const char*>(g_B) + (size_t)(nt + 1) * TILE_N * GROW_B;
            uint32_t dstb = smem_base + SMEM_Bo + (buf ^ 1) * SMEM_BT;
#pragma unroll
            for (int i = 0; i < 4; i++) {
                int idx = tid + i * 256;
                int row = idx >> 3, col = idx & 7;
                cp16(dstb + row * RS_B + col * 16, src + row * GROW_B + col * 16);
            }
            CP_COMMIT();
        }

#pragma unroll
        for (int mi = 0; mi < 2; mi++)
#pragma unroll
            for (int ni = 0; ni < 4; ni++)
                wmma::fill_fragment(acc[mi][ni], 0.0f);

        const __half* Bw = sB + buf * (SMEM_BT / 2) + (wn * 64) * RS_EL;
        const __half* Aw = sA + (wm * 32) * RS_EL;

#pragma unroll
        for (int ks = 0; ks < 4; ks++) {
            wmma::fragment<wmma::matrix_a, 16, 16, 16, __half, wmma::row_major> af[2];
            wmma::load_matrix_sync(af[0], Aw + ks * 16, RS_EL);
            wmma::load_matrix_sync(af[1], Aw + 16 * RS_EL + ks * 16, RS_EL);
#pragma unroll
            for (int ni = 0; ni < 4; ni++) {
                wmma::fragment<wmma::matrix_b, 16, 16, 16, __half, wmma::col_major> bf;
                wmma::load_matrix_sync(bf, Bw + (ni * 16) * RS_EL + ks * 16, RS_EL);
                wmma::mma_sync(acc[0][ni], af[0], bf, acc[0][ni]);
                wmma::mma_sync(acc[1][ni], af[1], bf, acc[1][ni]);
            }
        }

        if (fast) {
            // per row-slot: depth-4 tree max, then in-tile first-occurrence column
            const int cb = nt * TILE_N + wn * 64 + pcol0;
#pragma unroll
            for (int mi = 0; mi < 2; mi++) {
                float m0 = NEG_INF, m1 = NEG_INF;
#pragma unroll
                for (int ni = 0; ni < 4; ni++) {
                    const float* x = acc[mi][ni].x;
                    m0 = fmaxf(m0, fmaxf(fmaxf(x[0], x[1]), fmaxf(x[4], x[5])));
                    m1 = fmaxf(m1, fmaxf(fmaxf(x[2], x[3]), fmaxf(x[6], x[7])));
                }
                if (m0 > best[mi][0]) {
                    best[mi][0] = m0;
                    int c = 0x7FFFFFFF;
#pragma unroll
                    for (int ni = 0; ni < 4; ni++) {
                        const float* x = acc[mi][ni].x;
                        const int c0 = cb + ni * 16;
                        if (x[0] == m0) c = min(c, c0);
                        if (x[1] == m0) c = min(c, c0 + 1);
                        if (x[4] == m0) c = min(c, c0 + 8);
                        if (x[5] == m0) c = min(c, c0 + 9);
                    }
                    bidx[mi][0] = c;
                }
                if (m1 > best[mi][1]) {
                    best[mi][1] = m1;
                    int c = 0x7FFFFFFF;
#pragma unroll
                    for (int ni = 0; ni < 4; ni++) {
                        const float* x = acc[mi][ni].x;
                        const int c0 = cb + ni * 16;
                        if (x[2] == m1) c = min(c, c0);
                        if (x[3] == m1) c = min(c, c0 + 1);
                        if (x[6] == m1) c = min(c, c0 + 8);
                        if (x[7] == m1) c = min(c, c0 + 9);
                    }
                    bidx[mi][1] = c;
                }
            }
        } else {
            // generic fallback: exact per-value tracker (round-8 proven)
#pragma unroll
            for (int mi = 0; mi < 2; mi++)
#pragma unroll
                for (int ni = 0; ni < 4; ni++) {
                    const int cbase = nt * TILE_N + wn * 64 + ni * 16;
#pragma unroll
                    for (int k = 0; k < 8; k++) {
                        float v = acc[mi][ni].x[k];
                        const int c = cbase + (int)((pcolPack >> (4 * k)) & 15u);
                        if (rowBits & (1u << k)) {
                            if (v > best[mi][1]) { best[mi][1] = v; bidx[mi][1] = c; }
                        } else {
                            if (v > best[mi][0]) { best[mi][0] = v; bidx[mi][0] = c; }
                        }
                    }
                }
        }

        CP_WAIT0();
        __syncthreads();
    }

    // ---- merge trackers into per-row keys (exact monotonic key) ----
#pragma unroll
    for (int mi = 0; mi < 2; mi++) {
        int r0 = wm * 32 + mi * 16 + prow0;
        int r1 = wm * 32 + mi * 16 + prow1;
        atomicMax(&merge[r0], make_key(best[mi][0], bidx[mi][0]));
        if (prow1 != prow0)
            atomicMax(&merge[r1], make_key(best[mi][1], bidx[mi][1]));
    }
    __syncthreads();

    // ---- scatter outputs (one row per thread, threads 0..127) ----
    if (tid < 128) {
        const int r = rbase + tid;
        unsigned long long key = merge[tid];
        const int id = NSAMP - 1 - (int)(key & 0xFFFFFFFFull);

        const int b = r >> 14;
        const int rem = r & 16383;
        const int p = rem >> 2;
        const int ns = rem & 3;
        const float* pr = prior + (size_t)id * 8;
        float* zo = out + ((size_t)b * C2) * HW + p;
#pragma unroll
        for (int g = 0; g < 8; g++)
            zo[(size_t)(g * 4 + ns) * HW] = __ldg(pr + g);
        out[(size_t)4 * C2 * HW + (((size_t)b * 4 + ns) * HW + p)] = (float)id;
    }
}

extern "C" void kernel_launch(void* const* d_in, const int* in_sizes, int n_in,
                              void* d_out, int out_size) {
    const float* z     = (const float*)d_in[0];
    const float* prior = (const float*)d_in[1];
    float* out = (float*)d_out;

    cudaFuncSetAttribute(score_kernel, cudaFuncAttributeMaxDynamicSharedMemorySize, SMEM_TOTAL);

    prep_B_kernel<<<(NSAMP + 255) / 256, 256>>>(prior);
    score_kernel<<<NROWS / CTA_M, 256, SMEM_TOTAL>>>(z, prior, out);
    (void)in_sizes; (void)n_in; (void)out_size;
}